// round 13
// baseline (speedup 1.0000x reference)
#include <cuda_runtime.h>
#include <stdint.h>
#include <math.h>

// Problem constants
#define T_   4096
#define D_   128
#define H_   512
#define H3_  1536
#define WN_  4

#define GC   128      // CTAs in sequential kernel (all co-resident)
#define NT   256      // threads per CTA
#define NC   4        // columns owned per CTA

// ---------------- device scratch ----------------
__device__ float    g_XW [T_ * H3_];          //  25 MB : x@W + b
__device__ float    g_XWa[T_ * H_];           //   8 MB : x@Wa + ba
__device__ float    g_GWx[T_ * WN_ * H3_];    // 100 MB : emb[wid]@Ww + bw
__device__ float    g_cwt[(size_t)T_ * 2048]; //  32 MB : per-step c_w (write-once)
__device__ unsigned g_meta[T_];               // nact(3b) + [w(2b)|d(5b)] x4
__device__ unsigned g_flag[GC * 32];          // spread flags (late-phase barrier)
__device__ float4   g_rec4[2 * GC * 3];       // parity-buffered h|c records

// ---------------- acquire/release ops ----------------
__device__ __forceinline__ unsigned ld_acq(const unsigned* p) {
    unsigned v;
    asm volatile("ld.acquire.gpu.global.u32 %0, [%1];" : "=r"(v) : "l"(p) : "memory");
    return v;
}
__device__ __forceinline__ void st_rel(unsigned* p, unsigned v) {
    asm volatile("st.release.gpu.global.u32 [%0], %1;" :: "l"(p), "r"(v) : "memory");
}
__device__ __forceinline__ float4 ldacq4(const float* p) {
    float4 v;
    asm volatile("ld.acquire.gpu.global.v4.f32 {%0,%1,%2,%3}, [%4];"
                 : "=f"(v.x), "=f"(v.y), "=f"(v.z), "=f"(v.w) : "l"(p) : "memory");
    return v;
}
__device__ __forceinline__ void strel4(float* p, float x, float y, float z, float w) {
    asm volatile("st.release.gpu.global.v4.f32 [%0], {%1,%2,%3,%4};"
                 :: "l"(p), "f"(x), "f"(y), "f"(z), "f"(w) : "memory");
}

// ---------------- fast transcendentals (validated rel_err 3.5e-7) ----------------
__device__ __forceinline__ float fsig(float x) { return 1.0f / (1.0f + __expf(-x)); }
__device__ __forceinline__ float ftan(float x) {
    float ax = fabsf(x);
    float e  = __expf(-2.0f * ax);
    float t  = (1.0f - e) / (1.0f + e);
    return copysignf(t, x);
}

// ---------------- prep: reset + mask dtype detect + meta encode ----------------
__global__ void k_prep(const unsigned* __restrict__ mask32,
                       const void* __restrict__ mask,
                       const int*  __restrict__ wstarts)
{
    __shared__ int sflags;
    int tid = threadIdx.x;
    if (tid == 0) sflags = 7;
    for (int i = tid; i < GC * 32; i += 1024) g_flag[i] = 0;
    for (int i = tid; i < 2 * GC * 3; i += 1024) g_rec4[i] = make_float4(0, 0, 0, 0);
    __syncthreads();
    int bad = 0;
    for (int i = tid; i < 4096; i += 1024) {
        unsigned w = mask32[i];
        if (w > 1u)                      bad |= 1;   // not int32 0/1
        if (w != 0u && w != 0x3F800000u) bad |= 2;   // not float32 0/1
        if (w & 0xFEFEFEFEu)             bad |= 4;   // not uint8 0/1
    }
    if (bad) atomicAnd(&sflags, ~bad);
    __syncthreads();
    int flags = sflags;
    int mode = (flags & 1) ? 0 : ((flags & 2) ? 1 : 2);
    for (int t = tid; t < T_; t += 1024) {
        unsigned m = 0;
        int nact = 0;
        #pragma unroll
        for (int w = 0; w < WN_; ++w) {
            int i = t * WN_ + w;
            int on = (mode == 0) ? (((const int*)mask)[i] != 0)
                   : (mode == 1) ? (((const float*)mask)[i] != 0.0f)
                                 : (((const unsigned char*)mask)[i] != 0);
            if (on) {
                int d = t - wstarts[i];
                if (d < 1) d = 1;
                if (d > 31) d = 31;
                m |= (unsigned)(w | (d << 2)) << (3 + 7 * nact);
                ++nact;
            }
        }
        g_meta[t] = m | (unsigned)nact;
    }
}

// ---------------- precompute GEMM ----------------
__global__ __launch_bounds__(256) void k_gemm(
    const float* __restrict__ A, const int* __restrict__ gidx,
    const float* __restrict__ Bm, const float* __restrict__ bias,
    const float* __restrict__ B2, const float* __restrict__ bias2,
    int M, int K, int sel)
{
    float* C; int N, bn;
    const float* B  = Bm;
    const float* bs = bias;
    if (sel == 2) { C = g_GWx; N = H3_; bn = blockIdx.x * 64; }
    else {
        if (blockIdx.x < 24) { C = g_XW;  N = H3_; bn = blockIdx.x * 64; }
        else { C = g_XWa; N = H_; bn = (blockIdx.x - 24) * 64; B = B2; bs = bias2; }
    }

    __shared__ float As[16 * 130];
    __shared__ float Bs[16 * 64];

    int tid = threadIdx.x;
    int bm = blockIdx.y * 128;
    int tx = tid & 15;
    int ty = tid >> 4;

    float acc[8][4];
    #pragma unroll
    for (int i = 0; i < 8; ++i)
        #pragma unroll
        for (int j = 0; j < 4; ++j) acc[i][j] = 0.0f;

    for (int k0 = 0; k0 < K; k0 += 16) {
        #pragma unroll
        for (int i = 0; i < 2; ++i) {
            int f = tid + i * 256;
            int row = f >> 2, kq = (f & 3) * 4;
            int ar = gidx ? gidx[bm + row] : (bm + row);
            float4 v = *(const float4*)(A + (size_t)ar * K + k0 + kq);
            As[(kq + 0) * 130 + row] = v.x;
            As[(kq + 1) * 130 + row] = v.y;
            As[(kq + 2) * 130 + row] = v.z;
            As[(kq + 3) * 130 + row] = v.w;
        }
        {
            int row = tid >> 4, cq = (tid & 15) * 4;
            float4 v = *(const float4*)(B + (size_t)(k0 + row) * N + bn + cq);
            *(float4*)&Bs[row * 64 + cq] = v;
        }
        __syncthreads();
        #pragma unroll
        for (int kk = 0; kk < 16; ++kk) {
            float a[8], b[4];
            #pragma unroll
            for (int i = 0; i < 8; ++i) a[i] = As[kk * 130 + ty + i * 16];
            #pragma unroll
            for (int j = 0; j < 4; ++j) b[j] = Bs[kk * 64 + tx + j * 16];
            #pragma unroll
            for (int i = 0; i < 8; ++i)
                #pragma unroll
                for (int j = 0; j < 4; ++j) acc[i][j] += a[i] * b[j];
        }
        __syncthreads();
    }
    #pragma unroll
    for (int i = 0; i < 8; ++i) {
        int m = bm + ty + i * 16;
        #pragma unroll
        for (int j = 0; j < 4; ++j) {
            int n = bn + tx + j * 16;
            C[(size_t)m * N + n] = acc[i][j] + bs[n];
        }
    }
}

// ---------------- smem layout (float offsets) ----------------
#define SM_U     0                   // 3*512 float4  U slices [gate][k]
#define SM_UW    6144                // 3*512 float4  Uw slices
#define SM_UA    12288               // 512 float4    Ua slice [k]
#define SM_HP    14336               // 512  h(t-1)
#define SM_CP    14848               // 512  c(t-1)
#define SM_RB    15360               // 16 (3 gates x 4 cols, padded)
#define SM_RAL   15376               // 16 (4 words x 4 cols)
#define SM_RASH  15392               // 48 : d==1 word dots (step t)
#define SM_RASH2 15440               // 48 : shadow word dots (step t+1)
#define SM_CWO   15488               // 32 ([2 parity][4 words][4 cols])
#define SM_CPRV  15520               // 8 (4 used: c_prev own cols snapshot)
#define SM_CSSH  15528               // 16 (4 words x 4 cols)
#define SM_HC    15544               // 8 (h|c gather scratch for record store)
#define SM_META  15552               // 4096
#define SM_TOTF  (SM_META + 4096)
#define SMEM_BYTES (SM_TOTF * 4)

// 4-col warp dot: weights float4[512] smem, state float[512] (smem or global),
// bias 4 floats global (lane0 preloads); result(+bias) valid on lane0.
__device__ __forceinline__ float4 dotg(const float4* __restrict__ w,
                                       const float*  __restrict__ gh,
                                       const float*  __restrict__ gb,
                                       int lane) {
    float4 b = make_float4(0.f, 0.f, 0.f, 0.f);
    if (lane == 0) b = *(const float4*)gb;
    float ax = 0.f, ay = 0.f, az = 0.f, aw = 0.f;
    #pragma unroll
    for (int i = 0; i < 16; ++i) {
        int k = i * 32 + lane;
        float  hh = gh[k];
        float4 ww = w[k];
        ax += ww.x * hh; ay += ww.y * hh; az += ww.z * hh; aw += ww.w * hh;
    }
    #pragma unroll
    for (int o = 16; o > 0; o >>= 1) {
        ax += __shfl_xor_sync(0xFFFFFFFFu, ax, o);
        ay += __shfl_xor_sync(0xFFFFFFFFu, ay, o);
        az += __shfl_xor_sync(0xFFFFFFFFu, az, o);
        aw += __shfl_xor_sync(0xFFFFFFFFu, aw, o);
    }
    return make_float4(ax + b.x, ay + b.y, az + b.z, aw + b.w);
}

// fused 12-col word dot: 3 gates (f,i,g) x 4 cols share one row load stream.
// Writes 12 floats to dst (lane 0): [f0..3 | i0..3 | g0..3], bias added.
__device__ __forceinline__ void dot12(const float4* __restrict__ UWbase,
                                      const float*  __restrict__ gh,
                                      const float*  __restrict__ gb,
                                      int lane, float* __restrict__ dst) {
    float4 b0 = make_float4(0,0,0,0), b1 = b0, b2 = b0;
    if (lane == 0) {
        b0 = *(const float4*)(gb);
        b1 = *(const float4*)(gb + 512);
        b2 = *(const float4*)(gb + 1024);
    }
    float a[12];
    #pragma unroll
    for (int i = 0; i < 12; ++i) a[i] = 0.f;
    #pragma unroll
    for (int i = 0; i < 16; ++i) {
        int k = i * 32 + lane;
        float  hh = gh[k];
        float4 x = UWbase[k];
        float4 y = UWbase[512 + k];
        float4 z = UWbase[1024 + k];
        a[0] += x.x * hh; a[1] += x.y * hh; a[2]  += x.z * hh; a[3]  += x.w * hh;
        a[4] += y.x * hh; a[5] += y.y * hh; a[6]  += y.z * hh; a[7]  += y.w * hh;
        a[8] += z.x * hh; a[9] += z.y * hh; a[10] += z.z * hh; a[11] += z.w * hh;
    }
    #pragma unroll
    for (int o = 16; o > 0; o >>= 1)
        #pragma unroll
        for (int i = 0; i < 12; ++i)
            a[i] += __shfl_xor_sync(0xFFFFFFFFu, a[i], o);
    if (lane == 0) {
        dst[0] = a[0] + b0.x; dst[1] = a[1] + b0.y;
        dst[2] = a[2] + b0.z; dst[3] = a[3] + b0.w;
        dst[4] = a[4] + b1.x; dst[5] = a[5] + b1.y;
        dst[6] = a[6] + b1.z; dst[7] = a[7] + b1.w;
        dst[8] = a[8] + b2.x; dst[9] = a[9] + b2.y;
        dst[10] = a[10] + b2.z; dst[11] = a[11] + b2.w;
    }
}

__global__ __launch_bounds__(NT, 1) void k_seq(
    float* __restrict__ out,                 // [T, 1024] = hidden|cell
    const float* __restrict__ U,
    const float* __restrict__ Uw,
    const float* __restrict__ Ua,
    const float* __restrict__ h0,
    const float* __restrict__ c0)
{
    extern __shared__ float sm[];
    unsigned* s_meta = (unsigned*)(sm + SM_META);
    float4* U4   = (float4*)(sm + SM_U);
    float4* UW4  = (float4*)(sm + SM_UW);
    float4* UA4  = (float4*)(sm + SM_UA);
    float4* RB4  = (float4*)(sm + SM_RB);
    float4* RAL4 = (float4*)(sm + SM_RAL);

    const int c     = blockIdx.x;
    const int tid   = threadIdx.x;
    const int jbase = NC * c;
    const int warp  = tid >> 5, lane = tid & 31;

    // ---- one-time: weight column slices + meta table ----
    for (int idx = tid; idx < 3 * 512; idx += NT) {
        int gate = idx >> 9, k = idx & 511;
        U4 [gate * 512 + k] = *(const float4*)(U  + (size_t)k * H3_ + gate * 512 + jbase);
        UW4[gate * 512 + k] = *(const float4*)(Uw + (size_t)k * H3_ + gate * 512 + jbase);
    }
    for (int k = tid; k < 512; k += NT)
        UA4[k] = *(const float4*)(Ua + (size_t)k * H_ + jbase);
    for (int i = tid; i < T_; i += NT) s_meta[i] = g_meta[i];
    __syncthreads();

    unsigned seqA = 0;
    unsigned* myflag = &g_flag[c * 32];

    for (int t = 0; t < T_; ++t) {
        const unsigned meta = s_meta[t];
        const int nact = (int)(meta & 7u);
        const unsigned mN = (t + 1 < T_) ? s_meta[t + 1] : 0u;
        const int nactN = (int)(mN & 7u);

        int wT[4], dT[4], wN[4], dN[4];
        #pragma unroll
        for (int i = 0; i < 4; ++i) {
            unsigned f = meta >> (3 + 7 * i);
            wT[i] = (int)(f & 3u); dT[i] = (int)((f >> 2) & 31u);
            unsigned g = mN >> (3 + 7 * i);
            wN[i] = (int)(g & 3u); dN[i] = (int)((g >> 2) & 31u);
        }
        bool lateT = false;
        for (int i = 0; i < nact; ++i) lateT |= (dT[i] == 1);

        // ======== stage h_{t-1}, c_{t-1}: record poll IS the step barrier ======
        if (t == 0) {
            if (tid < 128) ((float4*)(sm + SM_HP))[tid] = ((const float4*)h0)[tid];
            else           ((float4*)(sm + SM_CP))[tid - 128] =
                               ((const float4*)c0)[tid - 128];
        } else {
            const float* base = (const float*)(g_rec4 + (size_t)(t & 1) * GC * 3);
            const unsigned sq = (unsigned)t;
            if (tid < 128) {
                const float* p0 = base + tid * 12;
                const float* p2 = base + tid * 12 + 8;
                float4 a, b2;
                for (;;) {
                    a  = ldacq4(p0);
                    b2 = ldacq4(p2);
                    if (__float_as_uint(a.x) == sq && __float_as_uint(b2.x) == sq)
                        break;
                }
                sm[SM_HP + tid * 4 + 0] = a.y;
                sm[SM_HP + tid * 4 + 1] = a.z;
                sm[SM_HP + tid * 4 + 2] = a.w;
                sm[SM_CP + tid * 4 + 2] = b2.y;
                sm[SM_CP + tid * 4 + 3] = b2.z;
            } else {
                int r = tid - 128;
                const float* p1 = base + r * 12 + 4;
                float4 b;
                for (;;) {
                    b = ldacq4(p1);
                    if (__float_as_uint(b.x) == sq) break;
                }
                sm[SM_HP + r * 4 + 3] = b.y;
                sm[SM_CP + r * 4 + 0] = b.z;
                sm[SM_CP + r * 4 + 1] = b.w;
            }
        }
        __syncthreads();

        // ======== round 1: everything depending only on rows <= t-1 ========
        const int base_d1 = 3 + nact;
        const int base_sh = base_d1 + (lateT ? nact : 0);
        const int ntasks  = base_sh + nactN + 1;
        for (int tk = warp; tk < ntasks; tk += 8) {
            if (tk < 3) {
                float4 r = dotg(U4 + (size_t)tk * 512, sm + SM_HP,
                                g_XW + (size_t)t * H3_ + tk * 512 + jbase, lane);
                if (lane == 0) RB4[tk] = r;
            } else if (tk < base_d1) {
                int wi = tk - 3;
                if (dT[wi] >= 2) {
                    float4 r = dotg(UA4, g_cwt + (size_t)t * 2048 + wi * 512,
                                    g_XWa + (size_t)t * H_ + jbase, lane);
                    if (lane == 0) RAL4[wi] = r;
                }
            } else if (tk < base_sh) {
                int wi = tk - base_d1;
                if (dT[wi] == 1)
                    dot12(UW4, sm + SM_HP,
                          g_GWx + ((size_t)t * WN_ + wT[wi]) * H3_ + jbase,
                          lane, sm + SM_RASH + wi * 12);
            } else if (tk < base_sh + nactN) {
                int wi = tk - base_sh;
                if (dN[wi] >= 2)
                    dot12(UW4, out + (size_t)(t + 1 - dN[wi]) * 1024,
                          g_GWx + ((size_t)(t + 1) * WN_ + wN[wi]) * H3_ + jbase,
                          lane, sm + SM_RASH2 + wi * 12);
            } else {
                if (lane == 0) {
                    #pragma unroll
                    for (int u = 0; u < 4; ++u)
                        sm[SM_CPRV + u] = sm[SM_CP + jbase + u];
                } else if (lane >= 2 && lane < 6) {
                    int wi = lane - 2;
                    if (wi < nactN && dN[wi] >= 2)
                        ((float4*)(sm + SM_CSSH))[wi] = *(const float4*)(
                            out + (size_t)(t + 1 - dN[wi]) * 1024 + 512 + jbase);
                }
            }
        }
        __syncthreads();

        // ======== late mid-barrier: publish d==1 c_w(t), then d==1 alphas ======
        if (lateT) {
            ++seqA;
            if (warp == 0) {
                if (lane >= 8 && lane < 12) {
                    int wi = lane - 8;
                    if (wi < nact && dT[wi] == 1) {
                        float cw[4];
                        #pragma unroll
                        for (int u = 0; u < 4; ++u) {
                            float fv = sm[SM_RASH + wi * 12 + 0 + u];
                            float iv = sm[SM_RASH + wi * 12 + 4 + u];
                            float gv = sm[SM_RASH + wi * 12 + 8 + u];
                            float cs = sm[SM_CPRV + u];
                            cw[u] = fsig(fv) * cs + fsig(iv) * ftan(gv);
                            sm[SM_CWO + (t & 1) * 16 + wi * 4 + u] = cw[u];
                        }
                        *(float4*)(g_cwt + (size_t)t * 2048 + wi * 512 + jbase) =
                            make_float4(cw[0], cw[1], cw[2], cw[3]);
                    }
                }
                __syncwarp();
                if (lane == 0) st_rel(myflag, seqA);
            }
            if (tid < GC) { while (ld_acq(&g_flag[tid * 32]) < seqA) {} }
            __syncthreads();
            for (int wi = warp; wi < nact; wi += 8) {
                if (dT[wi] == 1) {
                    float4 r = dotg(UA4, g_cwt + (size_t)t * 2048 + wi * 512,
                                    g_XWa + (size_t)t * H_ + jbase, lane);
                    if (lane == 0) RAL4[wi] = r;
                }
            }
            __syncthreads();
        }

        // ======== finalize (warp 0): combine lanes 0-3, shadow cw lanes 8-11,
        //          then lane 0 publishes the h|c record (release) ========
        if (warp == 0) {
            if (lane < 4) {
                int jl = lane;
                float ig = fsig(sm[SM_RB + 0 + jl]);
                float og = fsig(sm[SM_RB + 4 + jl]);
                float gt = ftan(sm[SM_RB + 8 + jl]);
                float c1;
                if (nact) {
                    float den = __expf(ig), num = den * gt;
                    for (int wi = 0; wi < nact; ++wi) {
                        float al = sm[SM_RAL + wi * 4 + jl];
                        float cw = sm[SM_CWO + (t & 1) * 16 + wi * 4 + jl];
                        float e  = __expf(fsig(al));
                        den += e; num += e * cw;
                    }
                    c1 = num / den;
                } else {
                    float cp = sm[SM_CPRV + jl];
                    c1 = (1.0f - ig) * cp + ig * gt;
                }
                float h1 = og * ftan(c1);
                out[(size_t)t * 1024 + jbase + jl]       = h1;
                out[(size_t)t * 1024 + 512 + jbase + jl] = c1;
                sm[SM_HC + jl]     = h1;
                sm[SM_HC + 4 + jl] = c1;
            } else if (lane >= 8 && lane < 12) {
                int wi = lane - 8;
                if (wi < nactN && dN[wi] >= 2) {
                    float cw[4];
                    #pragma unroll
                    for (int u = 0; u < 4; ++u) {
                        float fv = sm[SM_RASH2 + wi * 12 + 0 + u];
                        float iv = sm[SM_RASH2 + wi * 12 + 4 + u];
                        float gv = sm[SM_RASH2 + wi * 12 + 8 + u];
                        float cs = sm[SM_CSSH + wi * 4 + u];
                        cw[u] = fsig(fv) * cs + fsig(iv) * ftan(gv);
                        sm[SM_CWO + ((t + 1) & 1) * 16 + wi * 4 + u] = cw[u];
                    }
                    *(float4*)(g_cwt + (size_t)(t + 1) * 2048 + wi * 512 + jbase) =
                        make_float4(cw[0], cw[1], cw[2], cw[3]);
                }
            }
            __syncwarp();
            if (lane == 0) {
                float sq = __uint_as_float((unsigned)(t + 1));
                float* rp = (float*)(g_rec4 + ((size_t)((t + 1) & 1) * GC + c) * 3);
                strel4(rp,     sq, sm[SM_HC + 0], sm[SM_HC + 1], sm[SM_HC + 2]);
                strel4(rp + 4, sq, sm[SM_HC + 3], sm[SM_HC + 4], sm[SM_HC + 5]);
                strel4(rp + 8, sq, sm[SM_HC + 6], sm[SM_HC + 7], 0.0f);
            }
        }
        // no trailing barrier — next step's record poll is the barrier
    }
}

// ---------------- launch (4 kernels) ----------------
extern "C" void kernel_launch(void* const* d_in, const int* in_sizes, int n_in,
                              void* d_out, int out_size) {
    const float* x        = (const float*)d_in[0];
    const int*   word_ids = (const int*)  d_in[1];
    const int*   wstarts  = (const int*)  d_in[2];
    const void*  wmask    = (const void*) d_in[3];
    const float* h0       = (const float*)d_in[4];
    const float* c0       = (const float*)d_in[5];
    const float* emb      = (const float*)d_in[6];
    const float* W        = (const float*)d_in[7];
    const float* U        = (const float*)d_in[8];
    const float* b        = (const float*)d_in[9];
    const float* Wa       = (const float*)d_in[10];
    const float* Ua       = (const float*)d_in[11];
    const float* ba       = (const float*)d_in[12];
    const float* Ww       = (const float*)d_in[13];
    const float* Uw       = (const float*)d_in[14];
    const float* bw       = (const float*)d_in[15];
    float* out = (float*)d_out;

    k_prep<<<1, 1024>>>((const unsigned*)wmask, wmask, wstarts);

    dim3 gx(32, T_ / 128);
    k_gemm<<<gx, 256>>>(x, nullptr, W, b, Wa, ba, T_, D_, 3);
    dim3 gw(H3_ / 64, (T_ * WN_) / 128);
    k_gemm<<<gw, 256>>>(emb, word_ids, Ww, bw, nullptr, nullptr, T_ * WN_, 256, 2);

    static_assert(SMEM_BYTES < 220 * 1024, "smem");
    cudaFuncSetAttribute(k_seq, cudaFuncAttributeMaxDynamicSharedMemorySize,
                         SMEM_BYTES);
    k_seq<<<GC, NT, SMEM_BYTES>>>(out, U, Uw, Ua, h0, c0);
}

// round 15
// speedup vs baseline: 1.9017x; 1.9017x over previous
#include <cuda_runtime.h>
#include <stdint.h>
#include <math.h>

// Problem constants
#define T_   4096
#define D_   128
#define H_   512
#define H3_  1536
#define WN_  4

#define GC   64       // CTAs in sequential kernel
#define NT   512      // threads per CTA (16 warps)
#define NC   8        // columns owned per CTA (GC*NC = 512)

// ---------------- device scratch ----------------
__device__ float    g_XW [T_ * H3_];          //  25 MB : x@W + b
__device__ float    g_XWa[T_ * H_];           //   8 MB : x@Wa + ba
__device__ float    g_GWx[T_ * WN_ * H3_];    // 100 MB : emb[wid]@Ww + bw
__device__ float    g_cwt[(size_t)T_ * 2048]; //  32 MB : per-step c_w (write-once)
__device__ unsigned g_meta[T_];               // nact(3b) + [w(2b)|d(5b)] x4
__device__ unsigned g_flag[GC * 32];          // spread barrier flags (128B apart)

// ---------------- acquire/release flag ops ----------------
__device__ __forceinline__ unsigned ld_acq(const unsigned* p) {
    unsigned v;
    asm volatile("ld.acquire.gpu.global.u32 %0, [%1];" : "=r"(v) : "l"(p) : "memory");
    return v;
}
__device__ __forceinline__ void st_rel(unsigned* p, unsigned v) {
    asm volatile("st.release.gpu.global.u32 [%0], %1;" :: "l"(p), "r"(v) : "memory");
}
__device__ __forceinline__ void pf_l2(const float* p) {
    asm volatile("prefetch.global.L2 [%0];" :: "l"(p));
}

// ---------------- fast transcendentals (validated rel_err 3.5e-7) ----------------
__device__ __forceinline__ float fsig(float x) { return 1.0f / (1.0f + __expf(-x)); }
__device__ __forceinline__ float ftan(float x) {
    float ax = fabsf(x);
    float e  = __expf(-2.0f * ax);
    float t  = (1.0f - e) / (1.0f + e);
    return copysignf(t, x);
}

// ---------------- prep: flag reset + mask dtype detect + meta encode ----------------
__global__ void k_prep(const unsigned* __restrict__ mask32,
                       const void* __restrict__ mask,
                       const int*  __restrict__ wstarts)
{
    __shared__ int sflags;
    int tid = threadIdx.x;
    if (tid == 0) sflags = 7;
    for (int i = tid; i < GC * 32; i += 1024) g_flag[i] = 0;
    __syncthreads();
    int bad = 0;
    for (int i = tid; i < 4096; i += 1024) {
        unsigned w = mask32[i];
        if (w > 1u)                      bad |= 1;   // not int32 0/1
        if (w != 0u && w != 0x3F800000u) bad |= 2;   // not float32 0/1
        if (w & 0xFEFEFEFEu)             bad |= 4;   // not uint8 0/1
    }
    if (bad) atomicAnd(&sflags, ~bad);
    __syncthreads();
    int flags = sflags;
    int mode = (flags & 1) ? 0 : ((flags & 2) ? 1 : 2);
    for (int t = tid; t < T_; t += 1024) {
        unsigned m = 0;
        int nact = 0;
        #pragma unroll
        for (int w = 0; w < WN_; ++w) {
            int i = t * WN_ + w;
            int on = (mode == 0) ? (((const int*)mask)[i] != 0)
                   : (mode == 1) ? (((const float*)mask)[i] != 0.0f)
                                 : (((const unsigned char*)mask)[i] != 0);
            if (on) {
                int d = t - wstarts[i];
                if (d < 1) d = 1;
                if (d > 31) d = 31;
                m |= (unsigned)(w | (d << 2)) << (3 + 7 * nact);
                ++nact;
            }
        }
        g_meta[t] = m | (unsigned)nact;
    }
}

// ---------------- precompute GEMM ----------------
__global__ __launch_bounds__(256) void k_gemm(
    const float* __restrict__ A, const int* __restrict__ gidx,
    const float* __restrict__ Bm, const float* __restrict__ bias,
    const float* __restrict__ B2, const float* __restrict__ bias2,
    int M, int K, int sel)
{
    float* C; int N, bn;
    const float* B  = Bm;
    const float* bs = bias;
    if (sel == 2) { C = g_GWx; N = H3_; bn = blockIdx.x * 64; }
    else {
        if (blockIdx.x < 24) { C = g_XW;  N = H3_; bn = blockIdx.x * 64; }
        else { C = g_XWa; N = H_; bn = (blockIdx.x - 24) * 64; B = B2; bs = bias2; }
    }

    __shared__ float As[16 * 130];
    __shared__ float Bs[16 * 64];

    int tid = threadIdx.x;
    int bm = blockIdx.y * 128;
    int tx = tid & 15;
    int ty = tid >> 4;

    float acc[8][4];
    #pragma unroll
    for (int i = 0; i < 8; ++i)
        #pragma unroll
        for (int j = 0; j < 4; ++j) acc[i][j] = 0.0f;

    for (int k0 = 0; k0 < K; k0 += 16) {
        #pragma unroll
        for (int i = 0; i < 2; ++i) {
            int f = tid + i * 256;
            int row = f >> 2, kq = (f & 3) * 4;
            int ar = gidx ? gidx[bm + row] : (bm + row);
            float4 v = *(const float4*)(A + (size_t)ar * K + k0 + kq);
            As[(kq + 0) * 130 + row] = v.x;
            As[(kq + 1) * 130 + row] = v.y;
            As[(kq + 2) * 130 + row] = v.z;
            As[(kq + 3) * 130 + row] = v.w;
        }
        {
            int row = tid >> 4, cq = (tid & 15) * 4;
            float4 v = *(const float4*)(B + (size_t)(k0 + row) * N + bn + cq);
            *(float4*)&Bs[row * 64 + cq] = v;
        }
        __syncthreads();
        #pragma unroll
        for (int kk = 0; kk < 16; ++kk) {
            float a[8], b[4];
            #pragma unroll
            for (int i = 0; i < 8; ++i) a[i] = As[kk * 130 + ty + i * 16];
            #pragma unroll
            for (int j = 0; j < 4; ++j) b[j] = Bs[kk * 64 + tx + j * 16];
            #pragma unroll
            for (int i = 0; i < 8; ++i)
                #pragma unroll
                for (int j = 0; j < 4; ++j) acc[i][j] += a[i] * b[j];
        }
        __syncthreads();
    }
    #pragma unroll
    for (int i = 0; i < 8; ++i) {
        int m = bm + ty + i * 16;
        #pragma unroll
        for (int j = 0; j < 4; ++j) {
            int n = bn + tx + j * 16;
            C[(size_t)m * N + n] = acc[i][j] + bs[n];
        }
    }
}

// ---------------- smem layout (float offsets) ----------------
// U/UW: [gate*2+h][k] float4 (half-split: 4 contiguous cols per slice)
#define SM_U     0                   // 3*2*512*4 = 12288
#define SM_UW    12288               // 12288
#define SM_UA    24576               // 2*512*4 = 4096
#define SM_RB    28672               // 24 (3 gates x 8 cols), pad 32
#define SM_RAL   28704               // 32 (4 words x 8 cols)
#define SM_RASH  28736               // 96 : d==1 word dots (step t) [wi*24 + h*12]
#define SM_RASH2 28832               // 96 : shadow word dots (t+1)
#define SM_CWO   28928               // 64 ([2 parity][4 words][8 cols])
#define SM_CPRV  28992               // 8
#define SM_CSSH  29000               // 32 (4 words x 8 cols)
#define SM_META  29032               // 4096
#define SM_TOTF  (SM_META + 4096)
#define SMEM_BYTES (SM_TOTF * 4)

// 4-col warp dot: weights float4[512] contiguous smem slice, state float[512]
// (smem or global), bias 4 floats global (lane0 preloads); result on lane0.
__device__ __forceinline__ float4 dotg(const float4* __restrict__ w,
                                       const float*  __restrict__ gh,
                                       const float*  __restrict__ gb,
                                       int lane) {
    float4 b = make_float4(0.f, 0.f, 0.f, 0.f);
    if (lane == 0) b = *(const float4*)gb;
    float ax = 0.f, ay = 0.f, az = 0.f, aw = 0.f;
    #pragma unroll
    for (int i = 0; i < 16; ++i) {
        int k = i * 32 + lane;
        float  hh = gh[k];
        float4 ww = w[k];
        ax += ww.x * hh; ay += ww.y * hh; az += ww.z * hh; aw += ww.w * hh;
    }
    #pragma unroll
    for (int o = 16; o > 0; o >>= 1) {
        ax += __shfl_xor_sync(0xFFFFFFFFu, ax, o);
        ay += __shfl_xor_sync(0xFFFFFFFFu, ay, o);
        az += __shfl_xor_sync(0xFFFFFFFFu, az, o);
        aw += __shfl_xor_sync(0xFFFFFFFFu, aw, o);
    }
    return make_float4(ax + b.x, ay + b.y, az + b.z, aw + b.w);
}

// fused 12-value word dot: 3 gates x 4 cols share one row load stream.
// UWbase = UW slice for half h; gates are 1024 float4 apart.
// Writes 12 floats to dst (lane 0): [f0..3 | i0..3 | g0..3], bias added.
__device__ __forceinline__ void dot12(const float4* __restrict__ UWbase,
                                      const float*  __restrict__ gh,
                                      const float*  __restrict__ gb,
                                      int lane, float* __restrict__ dst) {
    float4 b0 = make_float4(0,0,0,0), b1 = b0, b2 = b0;
    if (lane == 0) {
        b0 = *(const float4*)(gb);
        b1 = *(const float4*)(gb + 512);
        b2 = *(const float4*)(gb + 1024);
    }
    float a[12];
    #pragma unroll
    for (int i = 0; i < 12; ++i) a[i] = 0.f;
    #pragma unroll
    for (int i = 0; i < 16; ++i) {
        int k = i * 32 + lane;
        float  hh = gh[k];
        float4 x = UWbase[k];
        float4 y = UWbase[1024 + k];
        float4 z = UWbase[2048 + k];
        a[0] += x.x * hh; a[1] += x.y * hh; a[2]  += x.z * hh; a[3]  += x.w * hh;
        a[4] += y.x * hh; a[5] += y.y * hh; a[6]  += y.z * hh; a[7]  += y.w * hh;
        a[8] += z.x * hh; a[9] += z.y * hh; a[10] += z.z * hh; a[11] += z.w * hh;
    }
    #pragma unroll
    for (int o = 16; o > 0; o >>= 1)
        #pragma unroll
        for (int i = 0; i < 12; ++i)
            a[i] += __shfl_xor_sync(0xFFFFFFFFu, a[i], o);
    if (lane == 0) {
        dst[0] = a[0] + b0.x; dst[1] = a[1] + b0.y;
        dst[2] = a[2] + b0.z; dst[3] = a[3] + b0.w;
        dst[4] = a[4] + b1.x; dst[5] = a[5] + b1.y;
        dst[6] = a[6] + b1.z; dst[7] = a[7] + b1.w;
        dst[8] = a[8] + b2.x; dst[9] = a[9] + b2.y;
        dst[10] = a[10] + b2.z; dst[11] = a[11] + b2.w;
    }
}

__global__ __launch_bounds__(NT, 1) void k_seq(
    float* __restrict__ out,                 // [T, 1024] = hidden|cell
    const float* __restrict__ U,
    const float* __restrict__ Uw,
    const float* __restrict__ Ua,
    const float* __restrict__ h0,
    const float* __restrict__ c0)
{
    extern __shared__ float sm[];
    unsigned* s_meta = (unsigned*)(sm + SM_META);
    float4* U4  = (float4*)(sm + SM_U);    // [(gate*2+h)*512 + k]
    float4* UW4 = (float4*)(sm + SM_UW);
    float4* UA4 = (float4*)(sm + SM_UA);   // [h*512 + k]

    const int c     = blockIdx.x;
    const int tid   = threadIdx.x;
    const int jbase = NC * c;
    const int warp  = tid >> 5, lane = tid & 31;

    // ---- one-time: weight column slices (half-split) + meta table ----
    for (int idx = tid; idx < 3 * 512; idx += NT) {
        int gate = idx >> 9, k = idx & 511;
        const float* pU  = U  + (size_t)k * H3_ + gate * 512 + jbase;
        const float* pUw = Uw + (size_t)k * H3_ + gate * 512 + jbase;
        U4 [(gate * 2 + 0) * 512 + k] = *(const float4*)pU;
        U4 [(gate * 2 + 1) * 512 + k] = *(const float4*)(pU + 4);
        UW4[(gate * 2 + 0) * 512 + k] = *(const float4*)pUw;
        UW4[(gate * 2 + 1) * 512 + k] = *(const float4*)(pUw + 4);
    }
    for (int k = tid; k < 512; k += NT) {
        const float* pUa = Ua + (size_t)k * H_ + jbase;
        UA4[k]       = *(const float4*)pUa;
        UA4[512 + k] = *(const float4*)(pUa + 4);
    }
    for (int i = tid; i < T_; i += NT) s_meta[i] = g_meta[i];
    __syncthreads();

    unsigned seqA = 0;
    unsigned* myflag = &g_flag[c * 32];

    for (int t = 0; t < T_; ++t) {
        const unsigned meta = s_meta[t];
        const int nact = (int)(meta & 7u);
        const unsigned mN = (t + 1 < T_) ? s_meta[t + 1] : 0u;
        const int nactN = (int)(mN & 7u);

        int wT[4], dT[4], wN[4], dN[4];
        #pragma unroll
        for (int i = 0; i < 4; ++i) {
            unsigned f = meta >> (3 + 7 * i);
            wT[i] = (int)(f & 3u); dT[i] = (int)((f >> 2) & 31u);
            unsigned g = mN >> (3 + 7 * i);
            wN[i] = (int)(g & 3u); dN[i] = (int)((g >> 2) & 31u);
        }
        bool lateT = false;
        for (int i = 0; i < nact; ++i) lateT |= (dT[i] == 1);

        const float* rowHprev = t ? (out + (size_t)(t - 1) * 1024) : h0;
        const float* rowCprev = t ? (out + (size_t)(t - 1) * 1024 + 512) : c0;

        // ======== round 1: everything depending only on rows <= t-1 ========
        // [0,6): gate dots (g,h)        [6, +2*nact): alpha dots (d>=2 only)
        // [+2*nact if lateT): fused d==1 word dots -> SM_RASH
        // [+2*nactN): fused shadow dots for t+1 (d>=2) -> SM_RASH2
        // [last]: micro loads + L2 prefetch for step t+2
        const int base_d1 = 6 + 2 * nact;
        const int base_sh = base_d1 + (lateT ? 2 * nact : 0);
        const int ntasks  = base_sh + 2 * nactN + 1;
        for (int tk = warp; tk < ntasks; tk += 16) {
            if (tk < 6) {
                int g = tk >> 1, h = tk & 1;
                float4 r = dotg(U4 + (size_t)(g * 2 + h) * 512, rowHprev,
                                g_XW + (size_t)t * H3_ + g * 512 + jbase + h * 4,
                                lane);
                if (lane == 0) *(float4*)(sm + SM_RB + g * 8 + h * 4) = r;
            } else if (tk < base_d1) {
                int q = tk - 6, wi = q >> 1, h = q & 1;
                if (dT[wi] >= 2) {
                    float4 r = dotg(UA4 + (size_t)h * 512,
                                    g_cwt + (size_t)t * 2048 + wi * 512,
                                    g_XWa + (size_t)t * H_ + jbase + h * 4, lane);
                    if (lane == 0) *(float4*)(sm + SM_RAL + wi * 8 + h * 4) = r;
                }
            } else if (tk < base_sh) {
                int q = tk - base_d1, wi = q >> 1, h = q & 1;
                if (dT[wi] == 1)
                    dot12(UW4 + (size_t)h * 512, rowHprev,
                          g_GWx + ((size_t)t * WN_ + wT[wi]) * H3_ + jbase + h * 4,
                          lane, sm + SM_RASH + wi * 24 + h * 12);
            } else if (tk < base_sh + 2 * nactN) {
                int q = tk - base_sh, wi = q >> 1, h = q & 1;
                if (dN[wi] >= 2)
                    dot12(UW4 + (size_t)h * 512,
                          out + (size_t)(t + 1 - dN[wi]) * 1024,
                          g_GWx + ((size_t)(t + 1) * WN_ + wN[wi]) * H3_
                                + jbase + h * 4,
                          lane, sm + SM_RASH2 + wi * 24 + h * 12);
            } else {
                if (lane < 2) {
                    ((float4*)(sm + SM_CPRV))[lane] =
                        *(const float4*)(rowCprev + jbase + lane * 4);
                } else if (lane < 10) {
                    int q = lane - 2, wi = q >> 1, h = q & 1;
                    if (wi < nactN && dN[wi] >= 2)
                        ((float4*)(sm + SM_CSSH))[wi * 2 + h] = *(const float4*)(
                            out + (size_t)(t + 1 - dN[wi]) * 1024 + 512
                                + jbase + h * 4);
                } else if (lane >= 16) {
                    int tp = t + 2;
                    if (tp < T_) {
                        if (lane < 19)
                            pf_l2(g_XW + (size_t)tp * H3_ + (lane - 16) * 512 + jbase);
                        else if (lane == 19)
                            pf_l2(g_XWa + (size_t)tp * H_ + jbase);
                        else {
                            unsigned mp = s_meta[tp];
                            int nap = (int)(mp & 7u);
                            int q = lane - 20, wi = q / 3, g = q - wi * 3;
                            if (wi < nap) {
                                int w = (int)((mp >> (3 + 7 * wi)) & 3u);
                                pf_l2(g_GWx + ((size_t)tp * WN_ + w) * H3_
                                            + g * 512 + jbase);
                            }
                        }
                    }
                }
            }
        }
        __syncthreads();

        // ======== late mid-barrier: publish d==1 c_w(t), then d==1 alphas ======
        if (lateT) {
            ++seqA;
            if (warp == 0) {
                if (lane >= 8 && lane < 16) {
                    int q = lane - 8, wi = q >> 1, h = q & 1;
                    if (wi < nact && dT[wi] == 1) {
                        float cw[4];
                        #pragma unroll
                        for (int u = 0; u < 4; ++u) {
                            float fv = sm[SM_RASH + wi * 24 + h * 12 + 0 + u];
                            float iv = sm[SM_RASH + wi * 24 + h * 12 + 4 + u];
                            float gv = sm[SM_RASH + wi * 24 + h * 12 + 8 + u];
                            float cs = sm[SM_CPRV + h * 4 + u];
                            cw[u] = fsig(fv) * cs + fsig(iv) * ftan(gv);
                            sm[SM_CWO + (t & 1) * 32 + wi * 8 + h * 4 + u] = cw[u];
                        }
                        *(float4*)(g_cwt + (size_t)t * 2048 + wi * 512
                                         + jbase + h * 4) =
                            make_float4(cw[0], cw[1], cw[2], cw[3]);
                    }
                }
                __syncwarp();
                if (lane == 0) st_rel(myflag, seqA);
            }
            if (tid < GC) { while (ld_acq(&g_flag[tid * 32]) < seqA) {} }
            __syncthreads();
            for (int q = warp; q < 2 * nact; q += 16) {
                int wi = q >> 1, h = q & 1;
                if (dT[wi] == 1) {
                    float4 r = dotg(UA4 + (size_t)h * 512,
                                    g_cwt + (size_t)t * 2048 + wi * 512,
                                    g_XWa + (size_t)t * H_ + jbase + h * 4, lane);
                    if (lane == 0) *(float4*)(sm + SM_RAL + wi * 8 + h * 4) = r;
                }
            }
            __syncthreads();
        }

        // ======== finalize (warp 0): combine lanes 0-7, shadow cw lanes 8-15 ====
        ++seqA;
        if (warp == 0) {
            if (lane < 8) {
                int jl = lane;
                float ig = fsig(sm[SM_RB + 0  + jl]);
                float og = fsig(sm[SM_RB + 8  + jl]);
                float gt = ftan(sm[SM_RB + 16 + jl]);
                float c1;
                if (nact) {
                    float den = __expf(ig), num = den * gt;
                    for (int wi = 0; wi < nact; ++wi) {
                        float al = sm[SM_RAL + wi * 8 + jl];
                        float cw = sm[SM_CWO + (t & 1) * 32 + wi * 8 + jl];
                        float e  = __expf(fsig(al));
                        den += e; num += e * cw;
                    }
                    c1 = num / den;
                } else {
                    float cp = sm[SM_CPRV + jl];
                    c1 = (1.0f - ig) * cp + ig * gt;
                }
                float h1 = og * ftan(c1);
                out[(size_t)t * 1024 + jbase + jl]       = h1;
                out[(size_t)t * 1024 + 512 + jbase + jl] = c1;
            } else if (lane < 16) {
                int q = lane - 8, wi = q >> 1, h = q & 1;
                if (wi < nactN && dN[wi] >= 2) {
                    float cw[4];
                    #pragma unroll
                    for (int u = 0; u < 4; ++u) {
                        float fv = sm[SM_RASH2 + wi * 24 + h * 12 + 0 + u];
                        float iv = sm[SM_RASH2 + wi * 24 + h * 12 + 4 + u];
                        float gv = sm[SM_RASH2 + wi * 24 + h * 12 + 8 + u];
                        float cs = sm[SM_CSSH + wi * 8 + h * 4 + u];
                        cw[u] = fsig(fv) * cs + fsig(iv) * ftan(gv);
                        sm[SM_CWO + ((t + 1) & 1) * 32 + wi * 8 + h * 4 + u] = cw[u];
                    }
                    *(float4*)(g_cwt + (size_t)(t + 1) * 2048 + wi * 512
                                     + jbase + h * 4) =
                        make_float4(cw[0], cw[1], cw[2], cw[3]);
                }
            }
            __syncwarp();
            if (lane == 0) st_rel(myflag, seqA);
        }
        // ======== trailing barrier (narrow flag poll) ========
        if (tid < GC) { while (ld_acq(&g_flag[tid * 32]) < seqA) {} }
        __syncthreads();
    }
}

// ---------------- launch (4 kernels) ----------------
extern "C" void kernel_launch(void* const* d_in, const int* in_sizes, int n_in,
                              void* d_out, int out_size) {
    const float* x        = (const float*)d_in[0];
    const int*   word_ids = (const int*)  d_in[1];
    const int*   wstarts  = (const int*)  d_in[2];
    const void*  wmask    = (const void*) d_in[3];
    const float* h0       = (const float*)d_in[4];
    const float* c0       = (const float*)d_in[5];
    const float* emb      = (const float*)d_in[6];
    const float* W        = (const float*)d_in[7];
    const float* U        = (const float*)d_in[8];
    const float* b        = (const float*)d_in[9];
    const float* Wa       = (const float*)d_in[10];
    const float* Ua       = (const float*)d_in[11];
    const float* ba       = (const float*)d_in[12];
    const float* Ww       = (const float*)d_in[13];
    const float* Uw       = (const float*)d_in[14];
    const float* bw       = (const float*)d_in[15];
    float* out = (float*)d_out;

    k_prep<<<1, 1024>>>((const unsigned*)wmask, wmask, wstarts);

    dim3 gx(32, T_ / 128);
    k_gemm<<<gx, 256>>>(x, nullptr, W, b, Wa, ba, T_, D_, 3);
    dim3 gw(H3_ / 64, (T_ * WN_) / 128);
    k_gemm<<<gw, 256>>>(emb, word_ids, Ww, bw, nullptr, nullptr, T_ * WN_, 256, 2);

    static_assert(SMEM_BYTES < 220 * 1024, "smem");
    cudaFuncSetAttribute(k_seq, cudaFuncAttributeMaxDynamicSharedMemorySize,
                         SMEM_BYTES);
    k_seq<<<GC, NT, SMEM_BYTES>>>(out, U, Uw, Ua, h0, c0);
}

// round 16
// speedup vs baseline: 2.1392x; 1.1249x over previous
#include <cuda_runtime.h>
#include <stdint.h>
#include <math.h>

// Problem constants
#define T_   4096
#define D_   128
#define H_   512
#define H3_  1536
#define WN_  4

#define GC   128      // CTAs in sequential kernel (all co-resident)
#define NT   256      // threads per CTA
#define NC   4        // columns owned per CTA

// ---------------- device scratch ----------------
__device__ float    g_XW [T_ * H3_];          //  25 MB : x@W + b
__device__ float    g_XWa[T_ * H_];           //   8 MB : x@Wa + ba
__device__ float    g_GWx[T_ * WN_ * H3_];    // 100 MB : emb[wid]@Ww + bw
__device__ float    g_cwt[(size_t)T_ * 2048]; //  32 MB : per-step c_w (write-once)
__device__ unsigned g_meta[T_];               // nact(3b) + [w(2b)|d(5b)] x4
__device__ unsigned g_flag[GC * 32];          // spread barrier flags (128B apart)

// ---------------- acquire/release flag ops ----------------
__device__ __forceinline__ unsigned ld_acq(const unsigned* p) {
    unsigned v;
    asm volatile("ld.acquire.gpu.global.u32 %0, [%1];" : "=r"(v) : "l"(p) : "memory");
    return v;
}
__device__ __forceinline__ void st_rel(unsigned* p, unsigned v) {
    asm volatile("st.release.gpu.global.u32 [%0], %1;" :: "l"(p), "r"(v) : "memory");
}
__device__ __forceinline__ void pf_l2(const float* p) {
    asm volatile("prefetch.global.L2 [%0];" :: "l"(p));
}

// ---------------- fast transcendentals (validated rel_err 3.5e-7) ----------------
__device__ __forceinline__ float fsig(float x) { return 1.0f / (1.0f + __expf(-x)); }
__device__ __forceinline__ float ftan(float x) {
    float ax = fabsf(x);
    float e  = __expf(-2.0f * ax);
    float t  = (1.0f - e) / (1.0f + e);
    return copysignf(t, x);
}

// ---------------- prep: flag reset + mask dtype detect + meta encode ----------------
__global__ void k_prep(const unsigned* __restrict__ mask32,
                       const void* __restrict__ mask,
                       const int*  __restrict__ wstarts)
{
    __shared__ int sflags;
    int tid = threadIdx.x;
    if (tid == 0) sflags = 7;
    for (int i = tid; i < GC * 32; i += 1024) g_flag[i] = 0;
    __syncthreads();
    int bad = 0;
    for (int i = tid; i < 4096; i += 1024) {
        unsigned w = mask32[i];
        if (w > 1u)                      bad |= 1;   // not int32 0/1
        if (w != 0u && w != 0x3F800000u) bad |= 2;   // not float32 0/1
        if (w & 0xFEFEFEFEu)             bad |= 4;   // not uint8 0/1
    }
    if (bad) atomicAnd(&sflags, ~bad);
    __syncthreads();
    int flags = sflags;
    int mode = (flags & 1) ? 0 : ((flags & 2) ? 1 : 2);
    for (int t = tid; t < T_; t += 1024) {
        unsigned m = 0;
        int nact = 0;
        #pragma unroll
        for (int w = 0; w < WN_; ++w) {
            int i = t * WN_ + w;
            int on = (mode == 0) ? (((const int*)mask)[i] != 0)
                   : (mode == 1) ? (((const float*)mask)[i] != 0.0f)
                                 : (((const unsigned char*)mask)[i] != 0);
            if (on) {
                int d = t - wstarts[i];
                if (d < 1) d = 1;
                if (d > 31) d = 31;
                m |= (unsigned)(w | (d << 2)) << (3 + 7 * nact);
                ++nact;
            }
        }
        g_meta[t] = m | (unsigned)nact;
    }
}

// ---------------- precompute GEMM ----------------
__global__ __launch_bounds__(256) void k_gemm(
    const float* __restrict__ A, const int* __restrict__ gidx,
    const float* __restrict__ Bm, const float* __restrict__ bias,
    const float* __restrict__ B2, const float* __restrict__ bias2,
    int M, int K, int sel)
{
    float* C; int N, bn;
    const float* B  = Bm;
    const float* bs = bias;
    if (sel == 2) { C = g_GWx; N = H3_; bn = blockIdx.x * 64; }
    else {
        if (blockIdx.x < 24) { C = g_XW;  N = H3_; bn = blockIdx.x * 64; }
        else { C = g_XWa; N = H_; bn = (blockIdx.x - 24) * 64; B = B2; bs = bias2; }
    }

    __shared__ float As[16 * 130];
    __shared__ float Bs[16 * 64];

    int tid = threadIdx.x;
    int bm = blockIdx.y * 128;
    int tx = tid & 15;
    int ty = tid >> 4;

    float acc[8][4];
    #pragma unroll
    for (int i = 0; i < 8; ++i)
        #pragma unroll
        for (int j = 0; j < 4; ++j) acc[i][j] = 0.0f;

    for (int k0 = 0; k0 < K; k0 += 16) {
        #pragma unroll
        for (int i = 0; i < 2; ++i) {
            int f = tid + i * 256;
            int row = f >> 2, kq = (f & 3) * 4;
            int ar = gidx ? gidx[bm + row] : (bm + row);
            float4 v = *(const float4*)(A + (size_t)ar * K + k0 + kq);
            As[(kq + 0) * 130 + row] = v.x;
            As[(kq + 1) * 130 + row] = v.y;
            As[(kq + 2) * 130 + row] = v.z;
            As[(kq + 3) * 130 + row] = v.w;
        }
        {
            int row = tid >> 4, cq = (tid & 15) * 4;
            float4 v = *(const float4*)(B + (size_t)(k0 + row) * N + bn + cq);
            *(float4*)&Bs[row * 64 + cq] = v;
        }
        __syncthreads();
        #pragma unroll
        for (int kk = 0; kk < 16; ++kk) {
            float a[8], b[4];
            #pragma unroll
            for (int i = 0; i < 8; ++i) a[i] = As[kk * 130 + ty + i * 16];
            #pragma unroll
            for (int j = 0; j < 4; ++j) b[j] = Bs[kk * 64 + tx + j * 16];
            #pragma unroll
            for (int i = 0; i < 8; ++i)
                #pragma unroll
                for (int j = 0; j < 4; ++j) acc[i][j] += a[i] * b[j];
        }
        __syncthreads();
    }
    #pragma unroll
    for (int i = 0; i < 8; ++i) {
        int m = bm + ty + i * 16;
        #pragma unroll
        for (int j = 0; j < 4; ++j) {
            int n = bn + tx + j * 16;
            C[(size_t)m * N + n] = acc[i][j] + bs[n];
        }
    }
}

// ---------------- smem layout (float offsets) ----------------
#define SM_U     0                   // 3*512 float4  U slices [gate][k]
#define SM_UW    6144                // 3*512 float4  Uw slices
#define SM_UA    12288               // 512 float4    Ua slice [k]
#define SM_RB    14336               // 3 float4      gate dots
#define SM_RAL   14352               // 4 float4      alpha dots
#define SM_RASH  14368               // 12 float4     d==1 word-gate dot results
#define SM_RASH2 14416               // 12 float4     shadow word dot results
#define SM_CWO   14464               // [2][4] float4 own c_w cols (parity)
#define SM_CPRV  14496               // 1 float4      c_prev own cols
#define SM_CSSH  14500               // 4 float4      shadow c_s own cols
#define SM_META  14520               // 4096 uint
#define SM_TOTF  (SM_META + 4096)
#define SMEM_BYTES (SM_TOTF * 4)

// 4-col warp dot: weights float4[512] smem, state float[512] (smem or global),
// bias 4 floats global (lane0 preloads); result(+bias) valid on lane0.
__device__ __forceinline__ float4 dotg(const float4* __restrict__ w,
                                       const float*  __restrict__ gh,
                                       const float*  __restrict__ gb,
                                       int lane) {
    float4 b = make_float4(0.f, 0.f, 0.f, 0.f);
    if (lane == 0) b = *(const float4*)gb;
    float ax = 0.f, ay = 0.f, az = 0.f, aw = 0.f;
    #pragma unroll
    for (int i = 0; i < 16; ++i) {
        int k = i * 32 + lane;
        float  hh = gh[k];
        float4 ww = w[k];
        ax += ww.x * hh; ay += ww.y * hh; az += ww.z * hh; aw += ww.w * hh;
    }
    #pragma unroll
    for (int o = 16; o > 0; o >>= 1) {
        ax += __shfl_xor_sync(0xFFFFFFFFu, ax, o);
        ay += __shfl_xor_sync(0xFFFFFFFFu, ay, o);
        az += __shfl_xor_sync(0xFFFFFFFFu, az, o);
        aw += __shfl_xor_sync(0xFFFFFFFFu, aw, o);
    }
    return make_float4(ax + b.x, ay + b.y, az + b.z, aw + b.w);
}

// fused 12-col word dot: 3 gates (f,i,g) x 4 cols share one row load stream.
// Results(+bias) valid on lane0 in a[12].
__device__ __forceinline__ void dot12(const float4* __restrict__ UWbase,
                                      const float*  __restrict__ gh,
                                      const float*  __restrict__ gb,
                                      int lane, float* __restrict__ a) {
    float4 b0 = make_float4(0,0,0,0), b1 = b0, b2 = b0;
    if (lane == 0) {
        b0 = *(const float4*)(gb);
        b1 = *(const float4*)(gb + 512);
        b2 = *(const float4*)(gb + 1024);
    }
    #pragma unroll
    for (int i = 0; i < 12; ++i) a[i] = 0.f;
    #pragma unroll
    for (int i = 0; i < 16; ++i) {
        int k = i * 32 + lane;
        float  hh = gh[k];
        float4 x = UWbase[k];
        float4 y = UWbase[512 + k];
        float4 z = UWbase[1024 + k];
        a[0] += x.x * hh; a[1] += x.y * hh; a[2]  += x.z * hh; a[3]  += x.w * hh;
        a[4] += y.x * hh; a[5] += y.y * hh; a[6]  += y.z * hh; a[7]  += y.w * hh;
        a[8] += z.x * hh; a[9] += z.y * hh; a[10] += z.z * hh; a[11] += z.w * hh;
    }
    #pragma unroll
    for (int o = 16; o > 0; o >>= 1)
        #pragma unroll
        for (int i = 0; i < 12; ++i)
            a[i] += __shfl_xor_sync(0xFFFFFFFFu, a[i], o);
    a[0] += b0.x; a[1] += b0.y; a[2]  += b0.z; a[3]  += b0.w;
    a[4] += b1.x; a[5] += b1.y; a[6]  += b1.z; a[7]  += b1.w;
    a[8] += b2.x; a[9] += b2.y; a[10] += b2.z; a[11] += b2.w;
}

__global__ __launch_bounds__(NT, 1) void k_seq(
    float* __restrict__ out,                 // [T, 1024] = hidden|cell
    const float* __restrict__ U,
    const float* __restrict__ Uw,
    const float* __restrict__ Ua,
    const float* __restrict__ h0,
    const float* __restrict__ c0)
{
    extern __shared__ float sm[];
    unsigned* s_meta = (unsigned*)(sm + SM_META);
    float4* U4   = (float4*)(sm + SM_U);
    float4* UW4  = (float4*)(sm + SM_UW);
    float4* UA4  = (float4*)(sm + SM_UA);
    float4* RB4  = (float4*)(sm + SM_RB);
    float4* RAL4 = (float4*)(sm + SM_RAL);
    float4* RASH4= (float4*)(sm + SM_RASH);
    float4* RASH24=(float4*)(sm + SM_RASH2);
    float4* CWO4 = (float4*)(sm + SM_CWO);
    float4* CPRV4= (float4*)(sm + SM_CPRV);
    float4* CSSH4= (float4*)(sm + SM_CSSH);

    const int c     = blockIdx.x;
    const int tid   = threadIdx.x;
    const int jbase = NC * c;
    const int warp  = tid >> 5, lane = tid & 31;

    // ---- one-time: weight column slices + meta table ----
    for (int idx = tid; idx < 3 * 512; idx += NT) {
        int gate = idx >> 9, k = idx & 511;
        U4 [gate * 512 + k] = *(const float4*)(U  + (size_t)k * H3_ + gate * 512 + jbase);
        UW4[gate * 512 + k] = *(const float4*)(Uw + (size_t)k * H3_ + gate * 512 + jbase);
    }
    for (int k = tid; k < 512; k += NT)
        UA4[k] = *(const float4*)(Ua + (size_t)k * H_ + jbase);
    for (int i = tid; i < T_; i += NT) s_meta[i] = g_meta[i];
    __syncthreads();

    unsigned seq = 0;
    unsigned* myflag = &g_flag[c * 32];

    for (int t = 0; t < T_; ++t) {
        const unsigned meta = s_meta[t];
        const int nact = (int)(meta & 7u);
        const unsigned mN = (t + 1 < T_) ? s_meta[t + 1] : 0u;
        const int nactN = (int)(mN & 7u);

        int wT[4], dT[4], wN[4], dN[4];
        #pragma unroll
        for (int i = 0; i < 4; ++i) {
            unsigned f = meta >> (3 + 7 * i);
            wT[i] = (int)(f & 3u); dT[i] = (int)((f >> 2) & 31u);
            unsigned g = mN >> (3 + 7 * i);
            wN[i] = (int)(g & 3u); dN[i] = (int)((g >> 2) & 31u);
        }
        bool lateT = false;
        for (int i = 0; i < nact; ++i) lateT |= (dT[i] == 1);

        const float* rowHprev = t ? (out + (size_t)(t - 1) * 1024) : h0;
        const float* rowCprev = t ? (out + (size_t)(t - 1) * 1024 + 512) : c0;

        // ======== round 1: everything that depends only on rows <= t-1 ========
        // [0,3): gate dots      [3,3+nact): alpha dots (d>=2 words only)
        // [3+nact, +nact): fused d==1 word dots (late steps)   -> SM_RASH
        // [.., +nactN): fused shadow word dots for t+1 (d>=2)  -> SM_RASH2
        // [last]: micro loads (c_prev, shadow c_s) + t+2 bias L2 prefetch
        const int base_d1 = 3 + nact;
        const int base_sh = base_d1 + (lateT ? nact : 0);
        const int ntasks  = base_sh + nactN + 1;
        for (int tk = warp; tk < ntasks; tk += 8) {
            if (tk < 3) {
                float4 r = dotg(U4 + (size_t)tk * 512, rowHprev,
                                g_XW + (size_t)t * H3_ + tk * 512 + jbase, lane);
                if (lane == 0) RB4[tk] = r;
            } else if (tk < base_d1) {
                int wi = tk - 3;
                if (dT[wi] >= 2) {
                    float4 r = dotg(UA4, g_cwt + (size_t)t * 2048 + wi * 512,
                                    g_XWa + (size_t)t * H_ + jbase, lane);
                    if (lane == 0) RAL4[wi] = r;
                }
            } else if (tk < base_sh) {
                int wi = tk - base_d1;
                if (dT[wi] == 1) {
                    float a[12];
                    dot12(UW4, rowHprev,
                          g_GWx + ((size_t)t * WN_ + wT[wi]) * H3_ + jbase,
                          lane, a);
                    if (lane == 0) {
                        RASH4[wi * 3 + 0] = make_float4(a[0], a[1], a[2],  a[3]);
                        RASH4[wi * 3 + 1] = make_float4(a[4], a[5], a[6],  a[7]);
                        RASH4[wi * 3 + 2] = make_float4(a[8], a[9], a[10], a[11]);
                    }
                }
            } else if (tk < base_sh + nactN) {
                int wi = tk - base_sh;
                if (dN[wi] >= 2) {
                    float a[12];
                    dot12(UW4, out + (size_t)(t + 1 - dN[wi]) * 1024,
                          g_GWx + ((size_t)(t + 1) * WN_ + wN[wi]) * H3_ + jbase,
                          lane, a);
                    if (lane == 0) {
                        RASH24[wi * 3 + 0] = make_float4(a[0], a[1], a[2],  a[3]);
                        RASH24[wi * 3 + 1] = make_float4(a[4], a[5], a[6],  a[7]);
                        RASH24[wi * 3 + 2] = make_float4(a[8], a[9], a[10], a[11]);
                    }
                }
            } else {
                if (lane == 0) {
                    CPRV4[0] = *(const float4*)(rowCprev + jbase);
                } else if (lane >= 2 && lane < 6) {
                    int wi = lane - 2;
                    if (wi < nactN && dN[wi] >= 2)
                        CSSH4[wi] = *(const float4*)(
                            out + (size_t)(t + 1 - dN[wi]) * 1024 + 512 + jbase);
                } else if (lane >= 16) {
                    // L2 prefetch of step t+2 bias lines (zero dependencies)
                    int tp = t + 2;
                    if (tp < T_) {
                        if (lane < 19) {
                            pf_l2(g_XW + (size_t)tp * H3_ + (lane - 16) * 512 + jbase);
                        } else if (lane == 19) {
                            pf_l2(g_XWa + (size_t)tp * H_ + jbase);
                        } else {
                            unsigned mp = s_meta[tp];
                            int nap = (int)(mp & 7u);
                            int q = lane - 20;           // 0..11
                            int wi = q / 3, g = q - wi * 3;
                            if (wi < nap) {
                                int w = (int)((mp >> (3 + 7 * wi)) & 3u);
                                pf_l2(g_GWx + ((size_t)tp * WN_ + w) * H3_
                                            + g * 512 + jbase);
                            }
                        }
                    }
                }
            }
        }
        __syncthreads();

        // ======== late mid-barrier: publish d==1 c_w(t), then d==1 alphas ======
        if (lateT) {
            ++seq;
            if (warp == 0) {
                if (lane >= 8 && lane < 12) {
                    int wi = lane - 8;
                    if (wi < nact && dT[wi] == 1) {
                        float4 f4v = RASH4[wi * 3 + 0];
                        float4 i4v = RASH4[wi * 3 + 1];
                        float4 g4v = RASH4[wi * 3 + 2];
                        float4 cs  = CPRV4[0];
                        float4 cw;
                        cw.x = fsig(f4v.x) * cs.x + fsig(i4v.x) * ftan(g4v.x);
                        cw.y = fsig(f4v.y) * cs.y + fsig(i4v.y) * ftan(g4v.y);
                        cw.z = fsig(f4v.z) * cs.z + fsig(i4v.z) * ftan(g4v.z);
                        cw.w = fsig(f4v.w) * cs.w + fsig(i4v.w) * ftan(g4v.w);
                        *(float4*)(g_cwt + (size_t)t * 2048 + wi * 512 + jbase) = cw;
                        CWO4[(t & 1) * 4 + wi] = cw;
                    }
                }
                __syncwarp();
                if (lane == 0) st_rel(myflag, seq);
            }
            if (tid < GC) { while (ld_acq(&g_flag[tid * 32]) < seq) {} }
            __syncthreads();
            // d==1 alpha dots
            for (int wi = warp; wi < nact; wi += 8) {
                if (dT[wi] == 1) {
                    float4 r = dotg(UA4, g_cwt + (size_t)t * 2048 + wi * 512,
                                    g_XWa + (size_t)t * H_ + jbase, lane);
                    if (lane == 0) RAL4[wi] = r;
                }
            }
            __syncthreads();
        }

        // ======== finalize (warp 0): combine lanes 0-3, shadow cw lanes 8-11 ====
        ++seq;
        if (warp == 0) {
            if (lane < 4) {
                int jl = lane;
                float ig = fsig(sm[SM_RB + 0 + jl]);
                float og = fsig(sm[SM_RB + 4 + jl]);
                float gt = ftan(sm[SM_RB + 8 + jl]);
                float c1;
                if (nact) {
                    float den = __expf(ig), num = den * gt;
                    for (int wi = 0; wi < nact; ++wi) {
                        float al = sm[SM_RAL + wi * 4 + jl];
                        float cw = sm[SM_CWO + (t & 1) * 16 + wi * 4 + jl];
                        float e  = __expf(fsig(al));
                        den += e; num += e * cw;
                    }
                    c1 = num / den;
                } else {
                    float cp = sm[SM_CPRV + jl];
                    c1 = (1.0f - ig) * cp + ig * gt;
                }
                float h1 = og * ftan(c1);
                out[(size_t)t * 1024 + jbase + jl]       = h1;
                out[(size_t)t * 1024 + 512 + jbase + jl] = c1;
            } else if (lane >= 8 && lane < 12) {
                int wi = lane - 8;
                if (wi < nactN && dN[wi] >= 2) {
                    float4 f4v = RASH24[wi * 3 + 0];
                    float4 i4v = RASH24[wi * 3 + 1];
                    float4 g4v = RASH24[wi * 3 + 2];
                    float4 cs  = CSSH4[wi];
                    float4 cw;
                    cw.x = fsig(f4v.x) * cs.x + fsig(i4v.x) * ftan(g4v.x);
                    cw.y = fsig(f4v.y) * cs.y + fsig(i4v.y) * ftan(g4v.y);
                    cw.z = fsig(f4v.z) * cs.z + fsig(i4v.z) * ftan(g4v.z);
                    cw.w = fsig(f4v.w) * cs.w + fsig(i4v.w) * ftan(g4v.w);
                    *(float4*)(g_cwt + (size_t)(t + 1) * 2048 + wi * 512 + jbase) = cw;
                    CWO4[((t + 1) & 1) * 4 + wi] = cw;
                }
            }
            __syncwarp();
            if (lane == 0) st_rel(myflag, seq);
        }
        // ======== barrier ========
        if (tid < GC) { while (ld_acq(&g_flag[tid * 32]) < seq) {} }
        __syncthreads();
    }
}

// ---------------- launch (4 kernels) ----------------
extern "C" void kernel_launch(void* const* d_in, const int* in_sizes, int n_in,
                              void* d_out, int out_size) {
    const float* x        = (const float*)d_in[0];
    const int*   word_ids = (const int*)  d_in[1];
    const int*   wstarts  = (const int*)  d_in[2];
    const void*  wmask    = (const void*) d_in[3];
    const float* h0       = (const float*)d_in[4];
    const float* c0       = (const float*)d_in[5];
    const float* emb      = (const float*)d_in[6];
    const float* W        = (const float*)d_in[7];
    const float* U        = (const float*)d_in[8];
    const float* b        = (const float*)d_in[9];
    const float* Wa       = (const float*)d_in[10];
    const float* Ua       = (const float*)d_in[11];
    const float* ba       = (const float*)d_in[12];
    const float* Ww       = (const float*)d_in[13];
    const float* Uw       = (const float*)d_in[14];
    const float* bw       = (const float*)d_in[15];
    float* out = (float*)d_out;

    k_prep<<<1, 1024>>>((const unsigned*)wmask, wmask, wstarts);

    dim3 gx(32, T_ / 128);
    k_gemm<<<gx, 256>>>(x, nullptr, W, b, Wa, ba, T_, D_, 3);
    dim3 gw(H3_ / 64, (T_ * WN_) / 128);
    k_gemm<<<gw, 256>>>(emb, word_ids, Ww, bw, nullptr, nullptr, T_ * WN_, 256, 2);

    static_assert(SMEM_BYTES < 220 * 1024, "smem");
    cudaFuncSetAttribute(k_seq, cudaFuncAttributeMaxDynamicSharedMemorySize,
                         SMEM_BYTES);
    k_seq<<<GC, NT, SMEM_BYTES>>>(out, U, Uw, Ua, h0, c0);
}

// round 17
// speedup vs baseline: 2.3124x; 1.0810x over previous
#include <cuda_runtime.h>
#include <stdint.h>
#include <math.h>

// Problem constants
#define T_   4096
#define D_   128
#define H_   512
#define H3_  1536
#define WN_  4

#define GC   128      // CTAs in sequential kernel (all co-resident)
#define NT   256      // threads per CTA
#define NC   4        // columns owned per CTA

// ---------------- device scratch ----------------
__device__ float    g_XW [T_ * H3_];          //  25 MB : x@W + b
__device__ float    g_XWa[T_ * H_];           //   8 MB : x@Wa + ba
__device__ float    g_GWx[T_ * WN_ * H3_];    // 100 MB : emb[wid]@Ww + bw
__device__ float    g_cwt[(size_t)T_ * 2048]; //  32 MB : per-step c_w (write-once)
__device__ unsigned g_meta[T_];               // nact(3b) + [w(2b)|d(5b)] x4
__device__ unsigned g_ctr;                    // monotonic barrier counter

// ---------------- acquire/release ops ----------------
__device__ __forceinline__ unsigned ld_acq(const unsigned* p) {
    unsigned v;
    asm volatile("ld.acquire.gpu.global.u32 %0, [%1];" : "=r"(v) : "l"(p) : "memory");
    return v;
}
__device__ __forceinline__ void red_add_rel(unsigned* p) {
    asm volatile("red.release.gpu.global.add.u32 [%0], %1;"
                 :: "l"(p), "r"(1u) : "memory");
}
__device__ __forceinline__ void pf_l2(const float* p) {
    asm volatile("prefetch.global.L2 [%0];" :: "l"(p));
}

// ---------------- fast transcendentals (validated rel_err 3.5e-7) ----------------
__device__ __forceinline__ float fsig(float x) { return 1.0f / (1.0f + __expf(-x)); }
__device__ __forceinline__ float ftan(float x) {
    float ax = fabsf(x);
    float e  = __expf(-2.0f * ax);
    float t  = (1.0f - e) / (1.0f + e);
    return copysignf(t, x);
}

// ---------------- prep: counter reset + mask dtype detect + meta encode ----------------
__global__ void k_prep(const unsigned* __restrict__ mask32,
                       const void* __restrict__ mask,
                       const int*  __restrict__ wstarts)
{
    __shared__ int sflags;
    int tid = threadIdx.x;
    if (tid == 0) { sflags = 7; g_ctr = 0; }
    __syncthreads();
    int bad = 0;
    for (int i = tid; i < 4096; i += 1024) {
        unsigned w = mask32[i];
        if (w > 1u)                      bad |= 1;   // not int32 0/1
        if (w != 0u && w != 0x3F800000u) bad |= 2;   // not float32 0/1
        if (w & 0xFEFEFEFEu)             bad |= 4;   // not uint8 0/1
    }
    if (bad) atomicAnd(&sflags, ~bad);
    __syncthreads();
    int flags = sflags;
    int mode = (flags & 1) ? 0 : ((flags & 2) ? 1 : 2);
    for (int t = tid; t < T_; t += 1024) {
        unsigned m = 0;
        int nact = 0;
        #pragma unroll
        for (int w = 0; w < WN_; ++w) {
            int i = t * WN_ + w;
            int on = (mode == 0) ? (((const int*)mask)[i] != 0)
                   : (mode == 1) ? (((const float*)mask)[i] != 0.0f)
                                 : (((const unsigned char*)mask)[i] != 0);
            if (on) {
                int d = t - wstarts[i];
                if (d < 1) d = 1;
                if (d > 31) d = 31;
                m |= (unsigned)(w | (d << 2)) << (3 + 7 * nact);
                ++nact;
            }
        }
        g_meta[t] = m | (unsigned)nact;
    }
}

// ---------------- precompute GEMM ----------------
__global__ __launch_bounds__(256) void k_gemm(
    const float* __restrict__ A, const int* __restrict__ gidx,
    const float* __restrict__ Bm, const float* __restrict__ bias,
    const float* __restrict__ B2, const float* __restrict__ bias2,
    int M, int K, int sel)
{
    float* C; int N, bn;
    const float* B  = Bm;
    const float* bs = bias;
    if (sel == 2) { C = g_GWx; N = H3_; bn = blockIdx.x * 64; }
    else {
        if (blockIdx.x < 24) { C = g_XW;  N = H3_; bn = blockIdx.x * 64; }
        else { C = g_XWa; N = H_; bn = (blockIdx.x - 24) * 64; B = B2; bs = bias2; }
    }

    __shared__ float As[16 * 130];
    __shared__ float Bs[16 * 64];

    int tid = threadIdx.x;
    int bm = blockIdx.y * 128;
    int tx = tid & 15;
    int ty = tid >> 4;

    float acc[8][4];
    #pragma unroll
    for (int i = 0; i < 8; ++i)
        #pragma unroll
        for (int j = 0; j < 4; ++j) acc[i][j] = 0.0f;

    for (int k0 = 0; k0 < K; k0 += 16) {
        #pragma unroll
        for (int i = 0; i < 2; ++i) {
            int f = tid + i * 256;
            int row = f >> 2, kq = (f & 3) * 4;
            int ar = gidx ? gidx[bm + row] : (bm + row);
            float4 v = *(const float4*)(A + (size_t)ar * K + k0 + kq);
            As[(kq + 0) * 130 + row] = v.x;
            As[(kq + 1) * 130 + row] = v.y;
            As[(kq + 2) * 130 + row] = v.z;
            As[(kq + 3) * 130 + row] = v.w;
        }
        {
            int row = tid >> 4, cq = (tid & 15) * 4;
            float4 v = *(const float4*)(B + (size_t)(k0 + row) * N + bn + cq);
            *(float4*)&Bs[row * 64 + cq] = v;
        }
        __syncthreads();
        #pragma unroll
        for (int kk = 0; kk < 16; ++kk) {
            float a[8], b[4];
            #pragma unroll
            for (int i = 0; i < 8; ++i) a[i] = As[kk * 130 + ty + i * 16];
            #pragma unroll
            for (int j = 0; j < 4; ++j) b[j] = Bs[kk * 64 + tx + j * 16];
            #pragma unroll
            for (int i = 0; i < 8; ++i)
                #pragma unroll
                for (int j = 0; j < 4; ++j) acc[i][j] += a[i] * b[j];
        }
        __syncthreads();
    }
    #pragma unroll
    for (int i = 0; i < 8; ++i) {
        int m = bm + ty + i * 16;
        #pragma unroll
        for (int j = 0; j < 4; ++j) {
            int n = bn + tx + j * 16;
            C[(size_t)m * N + n] = acc[i][j] + bs[n];
        }
    }
}

// ---------------- smem layout (float offsets) ----------------
#define SM_U     0                   // 3*512 float4  U slices [gate][k]
#define SM_UW    6144                // 3*512 float4  Uw slices
#define SM_UA    12288               // 512 float4    Ua slice [k]
#define SM_RB    14336               // 3 float4      gate dots
#define SM_RAL   14352               // 4 float4      alpha dots
#define SM_RASH  14368               // 12 float4     d==1 word-gate dot results
#define SM_RASH2 14416               // 12 float4     shadow word dot results
#define SM_CWO   14464               // [2][4] float4 own c_w cols (parity)
#define SM_CPRV  14496               // 1 float4      c_prev own cols
#define SM_CSSH  14500               // 4 float4      shadow c_s own cols
#define SM_META  14520               // 4096 uint
#define SM_TOTF  (SM_META + 4096)
#define SMEM_BYTES (SM_TOTF * 4)

// 4-col warp dot: weights float4[512] smem, state float[512] (smem or global),
// bias 4 floats global (lane0 preloads); result(+bias) valid on lane0.
__device__ __forceinline__ float4 dotg(const float4* __restrict__ w,
                                       const float*  __restrict__ gh,
                                       const float*  __restrict__ gb,
                                       int lane) {
    float4 b = make_float4(0.f, 0.f, 0.f, 0.f);
    if (lane == 0) b = *(const float4*)gb;
    float ax = 0.f, ay = 0.f, az = 0.f, aw = 0.f;
    #pragma unroll
    for (int i = 0; i < 16; ++i) {
        int k = i * 32 + lane;
        float  hh = gh[k];
        float4 ww = w[k];
        ax += ww.x * hh; ay += ww.y * hh; az += ww.z * hh; aw += ww.w * hh;
    }
    #pragma unroll
    for (int o = 16; o > 0; o >>= 1) {
        ax += __shfl_xor_sync(0xFFFFFFFFu, ax, o);
        ay += __shfl_xor_sync(0xFFFFFFFFu, ay, o);
        az += __shfl_xor_sync(0xFFFFFFFFu, az, o);
        aw += __shfl_xor_sync(0xFFFFFFFFu, aw, o);
    }
    return make_float4(ax + b.x, ay + b.y, az + b.z, aw + b.w);
}

// fused 12-col word dot: 3 gates (f,i,g) x 4 cols share one row load stream.
// Results(+bias) valid on lane0 in a[12].
__device__ __forceinline__ void dot12(const float4* __restrict__ UWbase,
                                      const float*  __restrict__ gh,
                                      const float*  __restrict__ gb,
                                      int lane, float* __restrict__ a) {
    float4 b0 = make_float4(0,0,0,0), b1 = b0, b2 = b0;
    if (lane == 0) {
        b0 = *(const float4*)(gb);
        b1 = *(const float4*)(gb + 512);
        b2 = *(const float4*)(gb + 1024);
    }
    #pragma unroll
    for (int i = 0; i < 12; ++i) a[i] = 0.f;
    #pragma unroll
    for (int i = 0; i < 16; ++i) {
        int k = i * 32 + lane;
        float  hh = gh[k];
        float4 x = UWbase[k];
        float4 y = UWbase[512 + k];
        float4 z = UWbase[1024 + k];
        a[0] += x.x * hh; a[1] += x.y * hh; a[2]  += x.z * hh; a[3]  += x.w * hh;
        a[4] += y.x * hh; a[5] += y.y * hh; a[6]  += y.z * hh; a[7]  += y.w * hh;
        a[8] += z.x * hh; a[9] += z.y * hh; a[10] += z.z * hh; a[11] += z.w * hh;
    }
    #pragma unroll
    for (int o = 16; o > 0; o >>= 1)
        #pragma unroll
        for (int i = 0; i < 12; ++i)
            a[i] += __shfl_xor_sync(0xFFFFFFFFu, a[i], o);
    a[0] += b0.x; a[1] += b0.y; a[2]  += b0.z; a[3]  += b0.w;
    a[4] += b1.x; a[5] += b1.y; a[6]  += b1.z; a[7]  += b1.w;
    a[8] += b2.x; a[9] += b2.y; a[10] += b2.z; a[11] += b2.w;
}

__global__ __launch_bounds__(NT, 1) void k_seq(
    float* __restrict__ out,                 // [T, 1024] = hidden|cell
    const float* __restrict__ U,
    const float* __restrict__ Uw,
    const float* __restrict__ Ua,
    const float* __restrict__ h0,
    const float* __restrict__ c0)
{
    extern __shared__ float sm[];
    unsigned* s_meta = (unsigned*)(sm + SM_META);
    float4* U4   = (float4*)(sm + SM_U);
    float4* UW4  = (float4*)(sm + SM_UW);
    float4* UA4  = (float4*)(sm + SM_UA);
    float4* RB4  = (float4*)(sm + SM_RB);
    float4* RAL4 = (float4*)(sm + SM_RAL);
    float4* RASH4= (float4*)(sm + SM_RASH);
    float4* RASH24=(float4*)(sm + SM_RASH2);
    float4* CWO4 = (float4*)(sm + SM_CWO);
    float4* CPRV4= (float4*)(sm + SM_CPRV);
    float4* CSSH4= (float4*)(sm + SM_CSSH);

    const int c     = blockIdx.x;
    const int tid   = threadIdx.x;
    const int jbase = NC * c;
    const int warp  = tid >> 5, lane = tid & 31;

    // ---- one-time: weight column slices + meta table ----
    for (int idx = tid; idx < 3 * 512; idx += NT) {
        int gate = idx >> 9, k = idx & 511;
        U4 [gate * 512 + k] = *(const float4*)(U  + (size_t)k * H3_ + gate * 512 + jbase);
        UW4[gate * 512 + k] = *(const float4*)(Uw + (size_t)k * H3_ + gate * 512 + jbase);
    }
    for (int k = tid; k < 512; k += NT)
        UA4[k] = *(const float4*)(Ua + (size_t)k * H_ + jbase);
    for (int i = tid; i < T_; i += NT) s_meta[i] = g_meta[i];
    __syncthreads();

    unsigned seq = 0;

    for (int t = 0; t < T_; ++t) {
        const unsigned meta = s_meta[t];
        const int nact = (int)(meta & 7u);
        const unsigned mN = (t + 1 < T_) ? s_meta[t + 1] : 0u;
        const int nactN = (int)(mN & 7u);

        int wT[4], dT[4], wN[4], dN[4];
        #pragma unroll
        for (int i = 0; i < 4; ++i) {
            unsigned f = meta >> (3 + 7 * i);
            wT[i] = (int)(f & 3u); dT[i] = (int)((f >> 2) & 31u);
            unsigned g = mN >> (3 + 7 * i);
            wN[i] = (int)(g & 3u); dN[i] = (int)((g >> 2) & 31u);
        }
        bool lateT = false;
        for (int i = 0; i < nact; ++i) lateT |= (dT[i] == 1);

        const float* rowHprev = t ? (out + (size_t)(t - 1) * 1024) : h0;
        const float* rowCprev = t ? (out + (size_t)(t - 1) * 1024 + 512) : c0;

        // ======== round 1: everything that depends only on rows <= t-1 ========
        // [0,3): gate dots      [3,3+nact): alpha dots (d>=2 words only)
        // [3+nact, +nact): fused d==1 word dots (late steps)   -> SM_RASH
        // [.., +nactN): fused shadow word dots for t+1 (d>=2)  -> SM_RASH2
        // [last]: micro loads (c_prev, shadow c_s) + t+2 bias L2 prefetch
        const int base_d1 = 3 + nact;
        const int base_sh = base_d1 + (lateT ? nact : 0);
        const int ntasks  = base_sh + nactN + 1;
        for (int tk = warp; tk < ntasks; tk += 8) {
            if (tk < 3) {
                float4 r = dotg(U4 + (size_t)tk * 512, rowHprev,
                                g_XW + (size_t)t * H3_ + tk * 512 + jbase, lane);
                if (lane == 0) RB4[tk] = r;
            } else if (tk < base_d1) {
                int wi = tk - 3;
                if (dT[wi] >= 2) {
                    float4 r = dotg(UA4, g_cwt + (size_t)t * 2048 + wi * 512,
                                    g_XWa + (size_t)t * H_ + jbase, lane);
                    if (lane == 0) RAL4[wi] = r;
                }
            } else if (tk < base_sh) {
                int wi = tk - base_d1;
                if (dT[wi] == 1) {
                    float a[12];
                    dot12(UW4, rowHprev,
                          g_GWx + ((size_t)t * WN_ + wT[wi]) * H3_ + jbase,
                          lane, a);
                    if (lane == 0) {
                        RASH4[wi * 3 + 0] = make_float4(a[0], a[1], a[2],  a[3]);
                        RASH4[wi * 3 + 1] = make_float4(a[4], a[5], a[6],  a[7]);
                        RASH4[wi * 3 + 2] = make_float4(a[8], a[9], a[10], a[11]);
                    }
                }
            } else if (tk < base_sh + nactN) {
                int wi = tk - base_sh;
                if (dN[wi] >= 2) {
                    float a[12];
                    dot12(UW4, out + (size_t)(t + 1 - dN[wi]) * 1024,
                          g_GWx + ((size_t)(t + 1) * WN_ + wN[wi]) * H3_ + jbase,
                          lane, a);
                    if (lane == 0) {
                        RASH24[wi * 3 + 0] = make_float4(a[0], a[1], a[2],  a[3]);
                        RASH24[wi * 3 + 1] = make_float4(a[4], a[5], a[6],  a[7]);
                        RASH24[wi * 3 + 2] = make_float4(a[8], a[9], a[10], a[11]);
                    }
                }
            } else {
                if (lane == 0) {
                    CPRV4[0] = *(const float4*)(rowCprev + jbase);
                } else if (lane >= 2 && lane < 6) {
                    int wi = lane - 2;
                    if (wi < nactN && dN[wi] >= 2)
                        CSSH4[wi] = *(const float4*)(
                            out + (size_t)(t + 1 - dN[wi]) * 1024 + 512 + jbase);
                } else if (lane >= 16) {
                    // L2 prefetch of step t+2 bias lines (zero dependencies)
                    int tp = t + 2;
                    if (tp < T_) {
                        if (lane < 19) {
                            pf_l2(g_XW + (size_t)tp * H3_ + (lane - 16) * 512 + jbase);
                        } else if (lane == 19) {
                            pf_l2(g_XWa + (size_t)tp * H_ + jbase);
                        } else {
                            unsigned mp = s_meta[tp];
                            int nap = (int)(mp & 7u);
                            int q = lane - 20;           // 0..11
                            int wi = q / 3, g = q - wi * 3;
                            if (wi < nap) {
                                int w = (int)((mp >> (3 + 7 * wi)) & 3u);
                                pf_l2(g_GWx + ((size_t)tp * WN_ + w) * H3_
                                            + g * 512 + jbase);
                            }
                        }
                    }
                }
            }
        }
        __syncthreads();

        // ======== late mid-barrier: publish d==1 c_w(t), then d==1 alphas ======
        if (lateT) {
            ++seq;
            if (warp == 0) {
                if (lane >= 8 && lane < 12) {
                    int wi = lane - 8;
                    if (wi < nact && dT[wi] == 1) {
                        float4 f4v = RASH4[wi * 3 + 0];
                        float4 i4v = RASH4[wi * 3 + 1];
                        float4 g4v = RASH4[wi * 3 + 2];
                        float4 cs  = CPRV4[0];
                        float4 cw;
                        cw.x = fsig(f4v.x) * cs.x + fsig(i4v.x) * ftan(g4v.x);
                        cw.y = fsig(f4v.y) * cs.y + fsig(i4v.y) * ftan(g4v.y);
                        cw.z = fsig(f4v.z) * cs.z + fsig(i4v.z) * ftan(g4v.z);
                        cw.w = fsig(f4v.w) * cs.w + fsig(i4v.w) * ftan(g4v.w);
                        *(float4*)(g_cwt + (size_t)t * 2048 + wi * 512 + jbase) = cw;
                        CWO4[(t & 1) * 4 + wi] = cw;
                    }
                }
                __syncwarp();
                if (lane == 0) red_add_rel(&g_ctr);
            }
            if (tid == 0) { while (ld_acq(&g_ctr) < seq * (unsigned)GC) {} }
            __syncthreads();
            // d==1 alpha dots
            for (int wi = warp; wi < nact; wi += 8) {
                if (dT[wi] == 1) {
                    float4 r = dotg(UA4, g_cwt + (size_t)t * 2048 + wi * 512,
                                    g_XWa + (size_t)t * H_ + jbase, lane);
                    if (lane == 0) RAL4[wi] = r;
                }
            }
            __syncthreads();
        }

        // ======== finalize (warp 0): combine lanes 0-3, shadow cw lanes 8-11 ====
        ++seq;
        if (warp == 0) {
            if (lane < 4) {
                int jl = lane;
                float ig = fsig(sm[SM_RB + 0 + jl]);
                float og = fsig(sm[SM_RB + 4 + jl]);
                float gt = ftan(sm[SM_RB + 8 + jl]);
                float c1;
                if (nact) {
                    float den = __expf(ig), num = den * gt;
                    for (int wi = 0; wi < nact; ++wi) {
                        float al = sm[SM_RAL + wi * 4 + jl];
                        float cw = sm[SM_CWO + (t & 1) * 16 + wi * 4 + jl];
                        float e  = __expf(fsig(al));
                        den += e; num += e * cw;
                    }
                    c1 = num / den;
                } else {
                    float cp = sm[SM_CPRV + jl];
                    c1 = (1.0f - ig) * cp + ig * gt;
                }
                float h1 = og * ftan(c1);
                out[(size_t)t * 1024 + jbase + jl]       = h1;
                out[(size_t)t * 1024 + 512 + jbase + jl] = c1;
            } else if (lane >= 8 && lane < 12) {
                int wi = lane - 8;
                if (wi < nactN && dN[wi] >= 2) {
                    float4 f4v = RASH24[wi * 3 + 0];
                    float4 i4v = RASH24[wi * 3 + 1];
                    float4 g4v = RASH24[wi * 3 + 2];
                    float4 cs  = CSSH4[wi];
                    float4 cw;
                    cw.x = fsig(f4v.x) * cs.x + fsig(i4v.x) * ftan(g4v.x);
                    cw.y = fsig(f4v.y) * cs.y + fsig(i4v.y) * ftan(g4v.y);
                    cw.z = fsig(f4v.z) * cs.z + fsig(i4v.z) * ftan(g4v.z);
                    cw.w = fsig(f4v.w) * cs.w + fsig(i4v.w) * ftan(g4v.w);
                    *(float4*)(g_cwt + (size_t)(t + 1) * 2048 + wi * 512 + jbase) = cw;
                    CWO4[((t + 1) & 1) * 4 + wi] = cw;
                }
            }
            __syncwarp();
            if (lane == 0) red_add_rel(&g_ctr);
        }
        // ======== barrier: single-thread counter poll + block broadcast ========
        if (tid == 0) { while (ld_acq(&g_ctr) < seq * (unsigned)GC) {} }
        __syncthreads();
    }
}

// ---------------- launch (4 kernels) ----------------
extern "C" void kernel_launch(void* const* d_in, const int* in_sizes, int n_in,
                              void* d_out, int out_size) {
    const float* x        = (const float*)d_in[0];
    const int*   word_ids = (const int*)  d_in[1];
    const int*   wstarts  = (const int*)  d_in[2];
    const void*  wmask    = (const void*) d_in[3];
    const float* h0       = (const float*)d_in[4];
    const float* c0       = (const float*)d_in[5];
    const float* emb      = (const float*)d_in[6];
    const float* W        = (const float*)d_in[7];
    const float* U        = (const float*)d_in[8];
    const float* b        = (const float*)d_in[9];
    const float* Wa       = (const float*)d_in[10];
    const float* Ua       = (const float*)d_in[11];
    const float* ba       = (const float*)d_in[12];
    const float* Ww       = (const float*)d_in[13];
    const float* Uw       = (const float*)d_in[14];
    const float* bw       = (const float*)d_in[15];
    float* out = (float*)d_out;

    k_prep<<<1, 1024>>>((const unsigned*)wmask, wmask, wstarts);

    dim3 gx(32, T_ / 128);
    k_gemm<<<gx, 256>>>(x, nullptr, W, b, Wa, ba, T_, D_, 3);
    dim3 gw(H3_ / 64, (T_ * WN_) / 128);
    k_gemm<<<gw, 256>>>(emb, word_ids, Ww, bw, nullptr, nullptr, T_ * WN_, 256, 2);

    static_assert(SMEM_BYTES < 220 * 1024, "smem");
    cudaFuncSetAttribute(k_seq, cudaFuncAttributeMaxDynamicSharedMemorySize,
                         SMEM_BYTES);
    k_seq<<<GC, NT, SMEM_BYTES>>>(out, U, Uw, Ua, h0, c0);
}